// round 1
// baseline (speedup 1.0000x reference)
#include <cuda_runtime.h>

// ---------------------------------------------------------------------------
// GIN: 3 layers of { rst = h + segment_sum(h[src], dst); h = MLP2(rst) }
// N=100000 nodes, E=1600000 edges, D=128.
//
// Strategy:
//   - Build CSR (dst -> list of src) once per launch via histogram + scan +
//     atomic bucket fill (int atomics only).
//   - Aggregate by GATHER (warp per node, lane owns a float4) -> no float
//     atomics, L2-resident reads.
//   - Fused 2-GEMM MLP per layer: 64-row tile, W / A-tile / hidden-tile in
//     dynamic smem, fp32 FFMA, 4x8 register micro-tile, pitch-129 A to avoid
//     bank conflicts.
// ---------------------------------------------------------------------------

#define DIM 128
#define MAXN 100000
#define MAXE 1600000
#define TILE_M 64
#define SCAN_CHUNK 2048   // 256 threads * 8 items
#define MAX_SCAN_BLOCKS 64

// scratch (device globals: no allocation allowed)
__device__ int   g_deg[MAXN];
__device__ int   g_rowptr[MAXN + 1];
__device__ int   g_cursor[MAXN];
__device__ int   g_col[MAXE];
__device__ int   g_bsum[MAX_SCAN_BLOCKS];
__device__ float g_rst[(size_t)MAXN * DIM];
__device__ float g_hA [(size_t)MAXN * DIM];
__device__ float g_hB [(size_t)MAXN * DIM];

// -------------------------- CSR build --------------------------------------

__global__ void k_zero_deg(int n) {
    int i = blockIdx.x * blockDim.x + threadIdx.x;
    if (i < n) g_deg[i] = 0;
}

__global__ void k_hist(const int* __restrict__ dst, int e) {
    int i = blockIdx.x * blockDim.x + threadIdx.x;
    if (i < e) atomicAdd(&g_deg[dst[i]], 1);
}

// per-chunk total
__global__ void k_scan_reduce(int n) {
    __shared__ int s[256];
    int tid = threadIdx.x;
    int base = blockIdx.x * SCAN_CHUNK + tid * 8;
    int tot = 0;
#pragma unroll
    for (int j = 0; j < 8; ++j) {
        int idx = base + j;
        tot += (idx < n) ? g_deg[idx] : 0;
    }
    s[tid] = tot;
    __syncthreads();
    for (int off = 128; off > 0; off >>= 1) {
        if (tid < off) s[tid] += s[tid + off];
        __syncthreads();
    }
    if (tid == 0) g_bsum[blockIdx.x] = s[0];
}

// exclusive scan of chunk totals (tiny)
__global__ void k_scan_bsum(int nb, int e, int n) {
    if (threadIdx.x == 0 && blockIdx.x == 0) {
        int run = 0;
        for (int b = 0; b < nb; ++b) {
            int t = g_bsum[b];
            g_bsum[b] = run;
            run += t;
        }
        g_rowptr[n] = e;
    }
}

// full exclusive scan: rowptr + cursor
__global__ void k_scan_final(int n) {
    __shared__ int s[256];
    int tid = threadIdx.x;
    int base = blockIdx.x * SCAN_CHUNK + tid * 8;
    int v[8];
    int run = 0;
#pragma unroll
    for (int j = 0; j < 8; ++j) {
        int idx = base + j;
        int t = (idx < n) ? g_deg[idx] : 0;
        v[j] = run;       // thread-local exclusive
        run += t;
    }
    int tot = run;
    s[tid] = tot;
    __syncthreads();
    // Hillis-Steele inclusive scan over thread totals
    for (int off = 1; off < 256; off <<= 1) {
        int add = (tid >= off) ? s[tid - off] : 0;
        __syncthreads();
        s[tid] += add;
        __syncthreads();
    }
    int texcl = s[tid] - tot;
    int pref = g_bsum[blockIdx.x] + texcl;
#pragma unroll
    for (int j = 0; j < 8; ++j) {
        int idx = base + j;
        if (idx < n) {
            int r = pref + v[j];
            g_rowptr[idx] = r;
            g_cursor[idx] = r;
        }
    }
}

__global__ void k_fill(const int* __restrict__ src, const int* __restrict__ dst, int e) {
    int i = blockIdx.x * blockDim.x + threadIdx.x;
    if (i < e) {
        int d = dst[i];
        int pos = atomicAdd(&g_cursor[d], 1);
        g_col[pos] = src[i];
    }
}

// ---------------------- aggregation (gather) --------------------------------
// warp per node, lane owns one float4 of the 128-dim row. EPS = 0.

__global__ void __launch_bounds__(256) k_agg(const float* __restrict__ hin,
                                             float* __restrict__ rst, int n) {
    int warp = (blockIdx.x * blockDim.x + threadIdx.x) >> 5;
    int lane = threadIdx.x & 31;
    if (warp >= n) return;
    const float4* __restrict__ h4 = (const float4*)hin;
    float4 a = h4[(size_t)warp * 32 + lane];  // self (1+eps)=1
    int s = g_rowptr[warp];
    int epos = g_rowptr[warp + 1];
    for (int i = s; i < epos; ++i) {
        int sn = g_col[i];
        float4 v = __ldg(&h4[(size_t)sn * 32 + lane]);
        a.x += v.x; a.y += v.y; a.z += v.z; a.w += v.w;
    }
    ((float4*)rst)[(size_t)warp * 32 + lane] = a;
}

// ---------------------- fused 2-GEMM MLP ------------------------------------
// out = act( act( A @ W1 + b1 ) @ W2 + b2 ), act = relu iff RELU.
// Block: 256 threads, TILE_M=64 rows x 128 cols.
// smem: sW[128*128] | sA[64*129] | sH[64*129]  (131584 bytes)

#define SA_PITCH 129
#define MLP_SMEM_BYTES ((16384 + 64 * SA_PITCH + 64 * SA_PITCH) * 4)

template <bool RELU>
__global__ void __launch_bounds__(256, 1)
k_mlp(const float* __restrict__ A,
      const float* __restrict__ W1, const float* __restrict__ b1,
      const float* __restrict__ W2, const float* __restrict__ b2,
      float* __restrict__ out, int n) {
    extern __shared__ float smem[];
    float* sW = smem;                 // 16384
    float* sA = sW + 16384;           // 64*129
    float* sH = sA + 64 * SA_PITCH;   // 64*129

    const int tid  = threadIdx.x;
    const int row0 = blockIdx.x * TILE_M;

    // load W1 (4096 float4 by 256 threads)
    {
        const float4* w4 = (const float4*)W1;
        float4* s4 = (float4*)sW;
#pragma unroll
        for (int it = 0; it < 16; ++it) s4[tid + it * 256] = w4[tid + it * 256];
    }
    // load A tile into pitch-129 smem (zero-fill OOB rows)
    {
#pragma unroll
        for (int it = 0; it < 8; ++it) {
            int i  = tid + it * 256;       // 0..2047
            int r  = i >> 5;
            int q  = i & 31;
            int rg = row0 + r;
            float4 f = (rg < n) ? ((const float4*)A)[(size_t)rg * 32 + q]
                                : make_float4(0.f, 0.f, 0.f, 0.f);
            float* p = &sA[r * SA_PITCH + (q << 2)];
            p[0] = f.x; p[1] = f.y; p[2] = f.z; p[3] = f.w;
        }
    }
    __syncthreads();

    const int trow = tid >> 4;   // 0..15 -> rows trow*4 .. +3
    const int tcol = tid & 15;   // 0..15 -> cols tcol*8 .. +7

    float acc[4][8];
    // ---- phase 1: h1 = act(A @ W1 + b1) ----
    {
        float bb[8];
#pragma unroll
        for (int j = 0; j < 8; ++j) bb[j] = b1[tcol * 8 + j];
#pragma unroll
        for (int i = 0; i < 4; ++i)
#pragma unroll
            for (int j = 0; j < 8; ++j) acc[i][j] = bb[j];
    }
#pragma unroll 4
    for (int k = 0; k < 128; ++k) {
        float a0 = sA[(trow * 4 + 0) * SA_PITCH + k];
        float a1 = sA[(trow * 4 + 1) * SA_PITCH + k];
        float a2 = sA[(trow * 4 + 2) * SA_PITCH + k];
        float a3 = sA[(trow * 4 + 3) * SA_PITCH + k];
        float4 p0 = *(const float4*)&sW[k * 128 + tcol * 8];
        float4 p1 = *(const float4*)&sW[k * 128 + tcol * 8 + 4];
        float av[4] = {a0, a1, a2, a3};
#pragma unroll
        for (int i = 0; i < 4; ++i) {
            acc[i][0] += av[i] * p0.x; acc[i][1] += av[i] * p0.y;
            acc[i][2] += av[i] * p0.z; acc[i][3] += av[i] * p0.w;
            acc[i][4] += av[i] * p1.x; acc[i][5] += av[i] * p1.y;
            acc[i][6] += av[i] * p1.z; acc[i][7] += av[i] * p1.w;
        }
    }
#pragma unroll
    for (int i = 0; i < 4; ++i)
#pragma unroll
        for (int j = 0; j < 8; ++j) {
            float v = acc[i][j];
            if (RELU) v = fmaxf(v, 0.f);
            sH[(trow * 4 + i) * SA_PITCH + tcol * 8 + j] = v;
        }
    __syncthreads();

    // overwrite sW with W2
    {
        const float4* w4 = (const float4*)W2;
        float4* s4 = (float4*)sW;
#pragma unroll
        for (int it = 0; it < 16; ++it) s4[tid + it * 256] = w4[tid + it * 256];
    }
    __syncthreads();

    // ---- phase 2: out = act(h1 @ W2 + b2) ----
    {
        float bb[8];
#pragma unroll
        for (int j = 0; j < 8; ++j) bb[j] = b2[tcol * 8 + j];
#pragma unroll
        for (int i = 0; i < 4; ++i)
#pragma unroll
            for (int j = 0; j < 8; ++j) acc[i][j] = bb[j];
    }
#pragma unroll 4
    for (int k = 0; k < 128; ++k) {
        float a0 = sH[(trow * 4 + 0) * SA_PITCH + k];
        float a1 = sH[(trow * 4 + 1) * SA_PITCH + k];
        float a2 = sH[(trow * 4 + 2) * SA_PITCH + k];
        float a3 = sH[(trow * 4 + 3) * SA_PITCH + k];
        float4 p0 = *(const float4*)&sW[k * 128 + tcol * 8];
        float4 p1 = *(const float4*)&sW[k * 128 + tcol * 8 + 4];
        float av[4] = {a0, a1, a2, a3};
#pragma unroll
        for (int i = 0; i < 4; ++i) {
            acc[i][0] += av[i] * p0.x; acc[i][1] += av[i] * p0.y;
            acc[i][2] += av[i] * p0.z; acc[i][3] += av[i] * p0.w;
            acc[i][4] += av[i] * p1.x; acc[i][5] += av[i] * p1.y;
            acc[i][6] += av[i] * p1.z; acc[i][7] += av[i] * p1.w;
        }
    }
#pragma unroll
    for (int i = 0; i < 4; ++i) {
        int rg = row0 + trow * 4 + i;
        if (rg < n) {
            float4 o0, o1;
            float v;
            v = acc[i][0]; o0.x = RELU ? fmaxf(v, 0.f) : v;
            v = acc[i][1]; o0.y = RELU ? fmaxf(v, 0.f) : v;
            v = acc[i][2]; o0.z = RELU ? fmaxf(v, 0.f) : v;
            v = acc[i][3]; o0.w = RELU ? fmaxf(v, 0.f) : v;
            v = acc[i][4]; o1.x = RELU ? fmaxf(v, 0.f) : v;
            v = acc[i][5]; o1.y = RELU ? fmaxf(v, 0.f) : v;
            v = acc[i][6]; o1.z = RELU ? fmaxf(v, 0.f) : v;
            v = acc[i][7]; o1.w = RELU ? fmaxf(v, 0.f) : v;
            ((float4*)out)[(size_t)rg * 32 + tcol * 2]     = o0;
            ((float4*)out)[(size_t)rg * 32 + tcol * 2 + 1] = o1;
        }
    }
}

// ---------------------------- host ------------------------------------------

extern "C" void kernel_launch(void* const* d_in, const int* in_sizes, int n_in,
                              void* d_out, int out_size) {
    const float* feat = (const float*)d_in[0];
    const float* W1   = (const float*)d_in[1];
    const float* b1   = (const float*)d_in[2];
    const float* W2   = (const float*)d_in[3];
    const float* b2   = (const float*)d_in[4];
    const int*   src  = (const int*)d_in[5];
    const int*   dst  = (const int*)d_in[6];

    const int n = in_sizes[0] / DIM;
    const int e = in_sizes[5];

    cudaFuncSetAttribute((const void*)k_mlp<true>,
                         cudaFuncAttributeMaxDynamicSharedMemorySize, MLP_SMEM_BYTES);
    cudaFuncSetAttribute((const void*)k_mlp<false>,
                         cudaFuncAttributeMaxDynamicSharedMemorySize, MLP_SMEM_BYTES);

    float *rst, *hA, *hB;
    cudaGetSymbolAddress((void**)&rst, g_rst);
    cudaGetSymbolAddress((void**)&hA,  g_hA);
    cudaGetSymbolAddress((void**)&hB,  g_hB);

    // ---- CSR build ----
    k_zero_deg<<<(n + 255) / 256, 256>>>(n);
    k_hist<<<(e + 255) / 256, 256>>>(dst, e);
    const int nb = (n + SCAN_CHUNK - 1) / SCAN_CHUNK;
    k_scan_reduce<<<nb, 256>>>(n);
    k_scan_bsum<<<1, 1>>>(nb, e, n);
    k_scan_final<<<nb, 256>>>(n);
    k_fill<<<(e + 255) / 256, 256>>>(src, dst, e);

    const int aggBlocks = (n + 7) / 8;          // 8 warps / block
    const int mlpBlocks = (n + TILE_M - 1) / TILE_M;

    // ---- layer 0 ----
    k_agg<<<aggBlocks, 256>>>(feat, rst, n);
    k_mlp<true><<<mlpBlocks, 256, MLP_SMEM_BYTES>>>(
        rst, W1 + 0 * DIM * DIM, b1 + 0 * DIM, W2 + 0 * DIM * DIM, b2 + 0 * DIM, hA, n);
    // ---- layer 1 ----
    k_agg<<<aggBlocks, 256>>>(hA, rst, n);
    k_mlp<true><<<mlpBlocks, 256, MLP_SMEM_BYTES>>>(
        rst, W1 + 1 * DIM * DIM, b1 + 1 * DIM, W2 + 1 * DIM * DIM, b2 + 1 * DIM, hB, n);
    // ---- layer 2 (no relu) ----
    k_agg<<<aggBlocks, 256>>>(hB, rst, n);
    k_mlp<false><<<mlpBlocks, 256, MLP_SMEM_BYTES>>>(
        rst, W1 + 2 * DIM * DIM, b1 + 2 * DIM, W2 + 2 * DIM * DIM, b2 + 2 * DIM,
        (float*)d_out, n);
}

// round 4
// speedup vs baseline: 1.4476x; 1.4476x over previous
#include <cuda_runtime.h>

// ---------------------------------------------------------------------------
// GIN: 3 layers of { rst = h + segment_sum(h[src], dst); h = MLP2(rst) }
// N=100000, E=1600000, D=128.
//   - CSR build per launch (int atomics only)
//   - Gather aggregation (warp/node, float4/lane), L2-resident
//   - Fused 2-GEMM MLP using packed fp32 FFMA2 (fma.rn.f32x2):
//     128-row tile, 512 threads, 8x4 micro-tile, f32x2 accumulators.
// ---------------------------------------------------------------------------

#define DIM 128
#define MAXN 100000
#define MAXE 1600000
#define TILE_M 128
#define SA_PITCH 132              // multiple of 4 (LDS.128 alignment), pad vs 128
#define MLP_THREADS 512
#define MLP_SMEM_FLOATS (128 * 128 + TILE_M * SA_PITCH)
#define MLP_SMEM_BYTES (MLP_SMEM_FLOATS * 4)
#define SCAN_CHUNK 2048
#define MAX_SCAN_BLOCKS 64

// scratch (device globals: no allocation allowed)
__device__ int   g_deg[MAXN];
__device__ int   g_rowptr[MAXN + 1];
__device__ int   g_cursor[MAXN];
__device__ int   g_col[MAXE];
__device__ int   g_bsum[MAX_SCAN_BLOCKS];
__device__ __align__(16) float g_rst[(size_t)MAXN * DIM];
__device__ __align__(16) float g_hA [(size_t)MAXN * DIM];
__device__ __align__(16) float g_hB [(size_t)MAXN * DIM];

// ------------------------- f32x2 helpers ------------------------------------

__device__ __forceinline__ unsigned long long pack2(float x, float y) {
    unsigned long long r;
    asm("mov.b64 %0, {%1, %2};" : "=l"(r) : "f"(x), "f"(y));
    return r;
}
__device__ __forceinline__ void unpack2(unsigned long long v, float& x, float& y) {
    asm("mov.b64 {%0, %1}, %2;" : "=f"(x), "=f"(y) : "l"(v));
}
__device__ __forceinline__ void fma2(unsigned long long& d,
                                     unsigned long long a, unsigned long long b) {
    asm("fma.rn.f32x2 %0, %1, %2, %0;" : "+l"(d) : "l"(a), "l"(b));
}

// -------------------------- CSR build ---------------------------------------

__global__ void k_zero_deg(int n) {
    int i = blockIdx.x * blockDim.x + threadIdx.x;
    if (i < n) g_deg[i] = 0;
}

__global__ void k_hist(const int* __restrict__ dst, int e) {
    int i = blockIdx.x * blockDim.x + threadIdx.x;
    if (i < e) atomicAdd(&g_deg[dst[i]], 1);
}

__global__ void k_scan_reduce(int n) {
    __shared__ int s[256];
    int tid = threadIdx.x;
    int base = blockIdx.x * SCAN_CHUNK + tid * 8;
    int tot = 0;
#pragma unroll
    for (int j = 0; j < 8; ++j) {
        int idx = base + j;
        tot += (idx < n) ? g_deg[idx] : 0;
    }
    s[tid] = tot;
    __syncthreads();
    for (int off = 128; off > 0; off >>= 1) {
        if (tid < off) s[tid] += s[tid + off];
        __syncthreads();
    }
    if (tid == 0) g_bsum[blockIdx.x] = s[0];
}

__global__ void k_scan_bsum(int nb, int e, int n) {
    __shared__ int s[64];
    int t = threadIdx.x;
    int v = (t < nb) ? g_bsum[t] : 0;
    s[t] = v;
    __syncthreads();
    for (int off = 1; off < 64; off <<= 1) {
        int a = (t >= off) ? s[t - off] : 0;
        __syncthreads();
        s[t] += a;
        __syncthreads();
    }
    if (t < nb) g_bsum[t] = s[t] - v;   // exclusive
    if (t == 0) g_rowptr[n] = e;
}

__global__ void k_scan_final(int n) {
    __shared__ int s[256];
    int tid = threadIdx.x;
    int base = blockIdx.x * SCAN_CHUNK + tid * 8;
    int v[8];
    int run = 0;
#pragma unroll
    for (int j = 0; j < 8; ++j) {
        int idx = base + j;
        int t = (idx < n) ? g_deg[idx] : 0;
        v[j] = run;
        run += t;
    }
    int tot = run;
    s[tid] = tot;
    __syncthreads();
    for (int off = 1; off < 256; off <<= 1) {
        int add = (tid >= off) ? s[tid - off] : 0;
        __syncthreads();
        s[tid] += add;
        __syncthreads();
    }
    int texcl = s[tid] - tot;
    int pref = g_bsum[blockIdx.x] + texcl;
#pragma unroll
    for (int j = 0; j < 8; ++j) {
        int idx = base + j;
        if (idx < n) {
            int r = pref + v[j];
            g_rowptr[idx] = r;
            g_cursor[idx] = r;
        }
    }
}

__global__ void k_fill(const int* __restrict__ src, const int* __restrict__ dst, int e) {
    int i = blockIdx.x * blockDim.x + threadIdx.x;
    if (i < e) {
        int d = dst[i];
        int pos = atomicAdd(&g_cursor[d], 1);
        g_col[pos] = src[i];
    }
}

// ---------------------- aggregation (gather) --------------------------------

__global__ void __launch_bounds__(256) k_agg(const float* __restrict__ hin,
                                             float* __restrict__ rst, int n) {
    int warp = (blockIdx.x * blockDim.x + threadIdx.x) >> 5;
    int lane = threadIdx.x & 31;
    if (warp >= n) return;
    const float4* __restrict__ h4 = (const float4*)hin;
    float4 a = h4[(size_t)warp * 32 + lane];  // self, (1+eps)=1
    int s = g_rowptr[warp];
    int epos = g_rowptr[warp + 1];
    for (int i = s; i < epos; ++i) {
        int sn = g_col[i];
        float4 v = __ldg(&h4[(size_t)sn * 32 + lane]);
        a.x += v.x; a.y += v.y; a.z += v.z; a.w += v.w;
    }
    ((float4*)rst)[(size_t)warp * 32 + lane] = a;
}

// ---------------------- fused 2-GEMM MLP (FFMA2) -----------------------------
// out = act( act( A @ W1 + b1 ) @ W2 + b2 ), act = relu iff RELU.
// 512 threads, 128-row tile, thread micro-tile 8 rows x 4 cols,
// accumulators as packed f32x2 column-pairs.

template <bool RELU>
__global__ void __launch_bounds__(MLP_THREADS, 1)
k_mlp(const float* __restrict__ A,
      const float* __restrict__ W1, const float* __restrict__ b1,
      const float* __restrict__ W2, const float* __restrict__ b2,
      float* __restrict__ out, int n) {
    extern __shared__ float smem[];
    float* sW = smem;                 // 128*128
    float* sA = sW + 128 * 128;       // 128*SA_PITCH

    const int tid  = threadIdx.x;
    const int row0 = blockIdx.x * TILE_M;

    // load W1 (4096 float4 by 512 threads)
    {
        const float4* w4 = (const float4*)W1;
        float4* s4 = (float4*)sW;
#pragma unroll
        for (int it = 0; it < 8; ++it) s4[tid + it * 512] = w4[tid + it * 512];
    }
    // load A tile into pitch-132 smem (zero-fill OOB rows)
    {
#pragma unroll
        for (int it = 0; it < 8; ++it) {
            int idx = tid + it * 512;       // 0..4095
            int r   = idx >> 5;
            int kq  = idx & 31;
            int rg  = row0 + r;
            float4 f = (rg < n) ? ((const float4*)A)[(size_t)rg * 32 + kq]
                                : make_float4(0.f, 0.f, 0.f, 0.f);
            *(float4*)&sA[r * SA_PITCH + kq * 4] = f;
        }
    }
    __syncthreads();

    const int trow = tid >> 5;   // 0..15 -> rows trow*8 .. +7
    const int tcol = tid & 31;   // 0..31 -> cols tcol*4 .. +3
    const int r0   = trow * 8;
    const int c0   = tcol * 4;

    unsigned long long acc[8][2];

    // ---- phase 1: h1 = act(A @ W1 + b1) ----
    {
        unsigned long long bb0 = pack2(b1[c0],     b1[c0 + 1]);
        unsigned long long bb1 = pack2(b1[c0 + 2], b1[c0 + 3]);
#pragma unroll
        for (int i = 0; i < 8; ++i) { acc[i][0] = bb0; acc[i][1] = bb1; }
    }
#pragma unroll 1
    for (int k0 = 0; k0 < 128; k0 += 4) {
        float4 a4[8];
#pragma unroll
        for (int i = 0; i < 8; ++i)
            a4[i] = *(const float4*)&sA[(r0 + i) * SA_PITCH + k0];
#pragma unroll
        for (int kk = 0; kk < 4; ++kk) {
            ulonglong2 w = *(const ulonglong2*)&sW[(k0 + kk) * 128 + c0];
#pragma unroll
            for (int i = 0; i < 8; ++i) {
                float av = ((const float*)&a4[i])[kk];
                unsigned long long aa = pack2(av, av);
                fma2(acc[i][0], aa, w.x);
                fma2(acc[i][1], aa, w.y);
            }
        }
    }
    __syncthreads();   // all reads of sA / sW complete

    // write h1 into sA (reuse); load W2 into sW
#pragma unroll
    for (int i = 0; i < 8; ++i) {
#pragma unroll
        for (int p = 0; p < 2; ++p) {
            float x, y;
            unpack2(acc[i][p], x, y);
            if (RELU) { x = fmaxf(x, 0.f); y = fmaxf(y, 0.f); }
            *(unsigned long long*)&sA[(r0 + i) * SA_PITCH + c0 + 2 * p] = pack2(x, y);
        }
    }
    {
        const float4* w4 = (const float4*)W2;
        float4* s4 = (float4*)sW;
#pragma unroll
        for (int it = 0; it < 8; ++it) s4[tid + it * 512] = w4[tid + it * 512];
    }
    __syncthreads();

    // ---- phase 2: out = act(h1 @ W2 + b2) ----
    {
        unsigned long long bb0 = pack2(b2[c0],     b2[c0 + 1]);
        unsigned long long bb1 = pack2(b2[c0 + 2], b2[c0 + 3]);
#pragma unroll
        for (int i = 0; i < 8; ++i) { acc[i][0] = bb0; acc[i][1] = bb1; }
    }
#pragma unroll 1
    for (int k0 = 0; k0 < 128; k0 += 4) {
        float4 a4[8];
#pragma unroll
        for (int i = 0; i < 8; ++i)
            a4[i] = *(const float4*)&sA[(r0 + i) * SA_PITCH + k0];
#pragma unroll
        for (int kk = 0; kk < 4; ++kk) {
            ulonglong2 w = *(const ulonglong2*)&sW[(k0 + kk) * 128 + c0];
#pragma unroll
            for (int i = 0; i < 8; ++i) {
                float av = ((const float*)&a4[i])[kk];
                unsigned long long aa = pack2(av, av);
                fma2(acc[i][0], aa, w.x);
                fma2(acc[i][1], aa, w.y);
            }
        }
    }

    // store
#pragma unroll
    for (int i = 0; i < 8; ++i) {
        int rg = row0 + r0 + i;
        if (rg < n) {
            float x0, y0, x1, y1;
            unpack2(acc[i][0], x0, y0);
            unpack2(acc[i][1], x1, y1);
            if (RELU) {
                x0 = fmaxf(x0, 0.f); y0 = fmaxf(y0, 0.f);
                x1 = fmaxf(x1, 0.f); y1 = fmaxf(y1, 0.f);
            }
            ((float4*)out)[(size_t)rg * 32 + tcol] = make_float4(x0, y0, x1, y1);
        }
    }
}

// ---------------------------- host ------------------------------------------

extern "C" void kernel_launch(void* const* d_in, const int* in_sizes, int n_in,
                              void* d_out, int out_size) {
    const float* feat = (const float*)d_in[0];
    const float* W1   = (const float*)d_in[1];
    const float* b1   = (const float*)d_in[2];
    const float* W2   = (const float*)d_in[3];
    const float* b2   = (const float*)d_in[4];
    const int*   src  = (const int*)d_in[5];
    const int*   dst  = (const int*)d_in[6];

    const int n = in_sizes[0] / DIM;
    const int e = in_sizes[5];

    cudaFuncSetAttribute((const void*)k_mlp<true>,
                         cudaFuncAttributeMaxDynamicSharedMemorySize, MLP_SMEM_BYTES);
    cudaFuncSetAttribute((const void*)k_mlp<false>,
                         cudaFuncAttributeMaxDynamicSharedMemorySize, MLP_SMEM_BYTES);

    float *rst, *hA, *hB;
    cudaGetSymbolAddress((void**)&rst, g_rst);
    cudaGetSymbolAddress((void**)&hA,  g_hA);
    cudaGetSymbolAddress((void**)&hB,  g_hB);

    // ---- CSR build ----
    k_zero_deg<<<(n + 255) / 256, 256>>>(n);
    k_hist<<<(e + 255) / 256, 256>>>(dst, e);
    const int nb = (n + SCAN_CHUNK - 1) / SCAN_CHUNK;
    k_scan_reduce<<<nb, 256>>>(n);
    k_scan_bsum<<<1, 64>>>(nb, e, n);
    k_scan_final<<<nb, 256>>>(n);
    k_fill<<<(e + 255) / 256, 256>>>(src, dst, e);

    const int aggBlocks = (n + 7) / 8;          // 8 warps / block
    const int mlpBlocks = (n + TILE_M - 1) / TILE_M;

    // ---- layer 0 ----
    k_agg<<<aggBlocks, 256>>>(feat, rst, n);
    k_mlp<true><<<mlpBlocks, MLP_THREADS, MLP_SMEM_BYTES>>>(
        rst, W1 + 0 * DIM * DIM, b1 + 0 * DIM, W2 + 0 * DIM * DIM, b2 + 0 * DIM, hA, n);
    // ---- layer 1 ----
    k_agg<<<aggBlocks, 256>>>(hA, rst, n);
    k_mlp<true><<<mlpBlocks, MLP_THREADS, MLP_SMEM_BYTES>>>(
        rst, W1 + 1 * DIM * DIM, b1 + 1 * DIM, W2 + 1 * DIM * DIM, b2 + 1 * DIM, hB, n);
    // ---- layer 2 (no relu) ----
    k_agg<<<aggBlocks, 256>>>(hB, rst, n);
    k_mlp<false><<<mlpBlocks, MLP_THREADS, MLP_SMEM_BYTES>>>(
        rst, W1 + 2 * DIM * DIM, b1 + 2 * DIM, W2 + 2 * DIM * DIM, b2 + 2 * DIM,
        (float*)d_out, n);
}